// round 15
// baseline (speedup 1.0000x reference)
#include <cuda_runtime.h>
#include <cuda_bf16.h>
#include <cstdint>
#include <math.h>

// ---------------- constants ----------------
#define LSEQ   3136        // 56*56
#define BATCH  8
#define TOK    25088       // LSEQ*BATCH
#define C1     256
#define C2     512
#define NHEAD  8
#define HDIM   32
#define BNS    0.9999950000374997f   // 1/sqrt(1+1e-5)

// ---------------- scratch (device globals; no allocation) ----------------
__device__ float g_res[TOK * C1];          // residual tokens [t,c]
__device__ float g_X3[TOK * C1];           // res + pos (tf32-rounded)
__device__ float g_X4[TOK * C1];           // conv/bn + pos (tf32-rounded)
__device__ float g_Q[TOK * C1];
__device__ float g_K[TOK * C1];
__device__ float g_V[TOK * C1];
__device__ float g_attn[TOK * C1];         // tf32-rounded
__device__ float g_out1[TOK * C1];
__device__ float g_out1tf[TOK * C1];       // tf32-rounded copy for FFN1
__device__ float g_sp[BATCH * C1 * LSEQ];  // final block output in [b,c,l] layout
__device__ float g_H[TOK * 1024];          // FFN hidden (tf32-rounded)
__device__ float g_part[64 * 8 * 64 * 32]; // partial KV
__device__ float g_psin[56 * 64];          // sin(r * omega_k)
__device__ float g_pcos[56 * 64];          // cos(r * omega_k)
// tf32-converted weights
__device__ float g_wc[C1 * C2];
__device__ float g_wq[C1 * C1];
__device__ float g_wk[C1 * C1];
__device__ float g_wv[C1 * C1];
__device__ float g_wo[C1 * C1];
__device__ float g_wl1[4 * C1 * C1];
__device__ float g_wl2[4 * C1 * C1];

// ---------------- helpers ----------------
__device__ __forceinline__ uint32_t f2tf(float f) {
    uint32_t u;
    asm("cvt.rna.tf32.f32 %0, %1;" : "=r"(u) : "f"(f));
    return u;
}
__device__ __forceinline__ float tfr(float f) { return __uint_as_float(f2tf(f)); }

__device__ __forceinline__ void cp16(void* dst_smem, const void* src) {
    uint32_t d = (uint32_t)__cvta_generic_to_shared(dst_smem);
    asm volatile("cp.async.cg.shared.global [%0], [%1], 16;\n" :: "r"(d), "l"(src));
}

__device__ __forceinline__ void ldsm4(uint32_t& r0, uint32_t& r1, uint32_t& r2, uint32_t& r3,
                                      uint32_t addr) {
    asm volatile("ldmatrix.sync.aligned.m8n8.x4.shared.b16 {%0,%1,%2,%3}, [%4];"
                 : "=r"(r0), "=r"(r1), "=r"(r2), "=r"(r3) : "r"(addr));
}

// small sincos tables: 56 positions x 64 frequencies
__global__ void pos_small_kernel(float* __restrict__ ps, float* __restrict__ pc) {
    int idx = blockIdx.x * 256 + threadIdx.x;   // 3584
    if (idx < 3584) {
        int r = idx >> 6, k = idx & 63;
        float om = expf(-(float)k * 0.14391156716f);   // ln(10000)/64
        float sv, cv;
        sincosf((float)r * om, &sv, &cv);
        ps[idx] = sv;
        pc[idx] = cv;
    }
}

__device__ __forceinline__ float posv(const float* __restrict__ ps, const float* __restrict__ pc,
                                      int l, int c) {
    int row = l / 56, col = l - row * 56;
    int k = c & 63;
    int rr = (c < 128) ? row : col;
    return (c & 64) ? pc[rr * 64 + k] : ps[rr * 64 + k];
}

// one merged tf32 conversion over all 7 weight tensors (float4 granules)
__global__ void tfconv_all(const float* __restrict__ wc, const float* __restrict__ wq,
                           const float* __restrict__ wk, const float* __restrict__ wv,
                           const float* __restrict__ wo, const float* __restrict__ wl1,
                           const float* __restrict__ wl2,
                           float* __restrict__ oc, float* __restrict__ oq,
                           float* __restrict__ ok, float* __restrict__ ov,
                           float* __restrict__ oo, float* __restrict__ ol1,
                           float* __restrict__ ol2) {
    int q = blockIdx.x * 256 + threadIdx.x;   // 229376 total
    const float* src; float* dst; int off;
    if (q < 32768)       { src = wc;  dst = oc;  off = q; }
    else if (q < 49152)  { src = wq;  dst = oq;  off = q - 32768; }
    else if (q < 65536)  { src = wk;  dst = ok;  off = q - 49152; }
    else if (q < 81920)  { src = wv;  dst = ov;  off = q - 65536; }
    else if (q < 98304)  { src = wo;  dst = oo;  off = q - 81920; }
    else if (q < 163840) { src = wl1; dst = ol1; off = q - 98304; }
    else                 { src = wl2; dst = ol2; off = q - 163840; }
    float4 v = *(const float4*)(src + off * 4);
    v.x = tfr(v.x); v.y = tfr(v.y); v.z = tfr(v.z); v.w = tfr(v.w);
    *(float4*)(dst + off * 4) = v;
}

// ---------------- fused pool(2x2) + transpose + pos: a3 -> res, X3 ----------------
__global__ void pool_transpose_tokens(const float* __restrict__ a3,
                                      float* __restrict__ res, float* __restrict__ X3,
                                      const float* __restrict__ ps, const float* __restrict__ pc) {
    __shared__ float s[32][33];
    int l0 = blockIdx.x << 5, c0 = blockIdx.y << 5, batch = blockIdx.z;
    int tx = threadIdx.x, ty = threadIdx.y;
    #pragma unroll
    for (int k = 0; k < 4; k++) {
        int c = c0 + ty + k * 8;
        int l = l0 + tx;
        int ly = l / 56, lx = l - ly * 56;
        const float* p = a3 + ((size_t)(batch * C1 + c) * 112 + 2 * ly) * 112 + 2 * lx;
        s[ty + k * 8][tx] = 0.25f * (p[0] + p[1] + p[112] + p[113]);
    }
    __syncthreads();
    #pragma unroll
    for (int k = 0; k < 4; k++) {
        int l = l0 + ty + k * 8, c = c0 + tx;
        float v = s[tx][ty + k * 8];
        int o = ((l << 3) + batch) * C1 + c;
        res[o] = v;
        X3[o] = tfr(v + posv(ps, pc, l, c));
    }
}

// ---------------- TF32 GEMM, 128x128 tile (generic, row-independent epilogues) ----------
// EPI: 0 = bias, 1 = bias+GELU(exact)+tf32-round (FFN hidden)
template<int K, int EPI>
__global__ void __launch_bounds__(256, 2) gemm_ca(
    const float* __restrict__ A, const float* __restrict__ W,
    const float* __restrict__ bias, float* __restrict__ C, int N) {
    extern __shared__ float sm[];
    float* AsB = sm;             // [2][128*36]
    float* BsB = sm + 2 * 4608;  // [2][128*36]
    int tid = threadIdx.x;
    int m0 = blockIdx.x << 7, n0 = blockIdx.y << 7;
    int warp = tid >> 5, lane = tid & 31;
    int wm = warp & 3, wn = warp >> 2;
    int g = lane >> 2, tig = lane & 3;

    int ar = tid >> 3, ac = (tid & 7) << 2;

    uint32_t smem_u = (uint32_t)__cvta_generic_to_shared(sm);
    uint32_t aoff[2], boff[4];
    #pragma unroll
    for (int mi = 0; mi < 2; mi++)
        aoff[mi] = ((wm * 32 + mi * 16 + (lane & 15)) * 36 + ((lane >> 4) << 2)) << 2;
    #pragma unroll
    for (int j = 0; j < 4; j++)
        boff[j] = (((wn * 64 + (2 * j + (lane >> 4)) * 8 + (lane & 7)) * 36 +
                    (((lane >> 3) & 1) << 2)) << 2) + 36864;

    float acc[2][8][4];
    #pragma unroll
    for (int i = 0; i < 2; i++)
        #pragma unroll
        for (int j = 0; j < 8; j++)
            #pragma unroll
            for (int q = 0; q < 4; q++) acc[i][j][q] = 0.f;

    const int NT = K / 32;

    {
        #pragma unroll
        for (int q = 0; q < 4; q++)
            cp16(AsB + (ar + q * 32) * 36 + ac, A + (size_t)(m0 + ar + q * 32) * K + ac);
        #pragma unroll
        for (int q = 0; q < 4; q++)
            cp16(BsB + (ar + q * 32) * 36 + ac, W + (size_t)(n0 + ar + q * 32) * K + ac);
        asm volatile("cp.async.commit_group;\n");
    }

    #pragma unroll 1
    for (int kt = 0; kt < NT; ++kt) {
        int cur = kt & 1;
        if (kt + 1 < NT) {
            int k0 = (kt + 1) * 32;
            float* Ad = AsB + (cur ^ 1) * 4608;
            float* Bd = BsB + (cur ^ 1) * 4608;
            #pragma unroll
            for (int q = 0; q < 4; q++)
                cp16(Ad + (ar + q * 32) * 36 + ac, A + (size_t)(m0 + ar + q * 32) * K + k0 + ac);
            #pragma unroll
            for (int q = 0; q < 4; q++)
                cp16(Bd + (ar + q * 32) * 36 + ac, W + (size_t)(n0 + ar + q * 32) * K + k0 + ac);
            asm volatile("cp.async.commit_group;\n");
            asm volatile("cp.async.wait_group 1;\n");
        } else {
            asm volatile("cp.async.wait_group 0;\n");
        }
        __syncthreads();

        uint32_t abase = smem_u + cur * 18432;
        uint32_t bbase = smem_u + cur * 18432;
        #pragma unroll
        for (int ks = 0; ks < 4; ks++) {
            uint32_t kkb = ks * 32;
            uint32_t a[2][4], b[8][2];
            ldsm4(a[0][0], a[0][1], a[0][2], a[0][3], abase + aoff[0] + kkb);
            ldsm4(a[1][0], a[1][1], a[1][2], a[1][3], abase + aoff[1] + kkb);
            ldsm4(b[0][0], b[0][1], b[1][0], b[1][1], bbase + boff[0] + kkb);
            ldsm4(b[2][0], b[2][1], b[3][0], b[3][1], bbase + boff[1] + kkb);
            ldsm4(b[4][0], b[4][1], b[5][0], b[5][1], bbase + boff[2] + kkb);
            ldsm4(b[6][0], b[6][1], b[7][0], b[7][1], bbase + boff[3] + kkb);
            #pragma unroll
            for (int mi = 0; mi < 2; mi++)
                #pragma unroll
                for (int nf = 0; nf < 8; nf++)
                    asm volatile(
                        "mma.sync.aligned.m16n8k8.row.col.f32.tf32.tf32.f32 "
                        "{%0,%1,%2,%3}, {%4,%5,%6,%7}, {%8,%9}, {%0,%1,%2,%3};"
                        : "+f"(acc[mi][nf][0]), "+f"(acc[mi][nf][1]),
                          "+f"(acc[mi][nf][2]), "+f"(acc[mi][nf][3])
                        : "r"(a[mi][0]), "r"(a[mi][1]), "r"(a[mi][2]), "r"(a[mi][3]),
                          "r"(b[nf][0]), "r"(b[nf][1]));
        }
        __syncthreads();
    }

    #pragma unroll
    for (int mi = 0; mi < 2; mi++) {
        #pragma unroll
        for (int nf = 0; nf < 8; nf++) {
            int n = n0 + wn * 64 + nf * 8 + tig * 2;
            int r0 = m0 + wm * 32 + mi * 16 + g;
            #pragma unroll
            for (int h = 0; h < 2; h++) {
                int m = r0 + h * 8;
                float v0 = acc[mi][nf][h * 2 + 0] + bias[n];
                float v1 = acc[mi][nf][h * 2 + 1] + bias[n + 1];
                if (EPI == 1) {
                    v0 = tfr(0.5f * v0 * (1.0f + erff(v0 * 0.70710678118654752f)));
                    v1 = tfr(0.5f * v1 * (1.0f + erff(v1 * 0.70710678118654752f)));
                }
                *(float2*)(C + (size_t)m * N + n) = make_float2(v0, v1);
            }
        }
    }
}

// ---------------- TF32 GEMM, 64x256 tile with fused row-norm epilogue ----------------
// MODE 0: out = L2norm(LayerNorm(acc+bias; lw,lb))               (Q/K projection)
// MODE 1: out = base + LayerNorm(acc+bias; lw,lb); opt out_tf    (O-proj)
// MODE 2: same math as MODE 1, but out written in SPATIAL [b,c,l] layout (FFN2)
template<int K, int MODE>
__global__ void __launch_bounds__(256, 2) gemm_ln(
    const float* __restrict__ A, const float* __restrict__ W,
    const float* __restrict__ bias, const float* __restrict__ lw,
    const float* __restrict__ lb, const float* __restrict__ base,
    float* __restrict__ out, float* __restrict__ out_tf) {
    extern __shared__ float sm[];
    int tid = threadIdx.x;
    int m0 = blockIdx.x << 6;
    int warp = tid >> 5, lane = tid & 31;
    int wm = warp & 1, wn = warp >> 1;
    int g = lane >> 2, tig = lane & 3;

    int ar = tid >> 3, ac = (tid & 7) << 2;

    uint32_t smem_u = (uint32_t)__cvta_generic_to_shared(sm);
    uint32_t aoff[2], boff[4];
    #pragma unroll
    for (int mi = 0; mi < 2; mi++)
        aoff[mi] = ((wm * 32 + mi * 16 + (lane & 15)) * 36 + ((lane >> 4) << 2)) << 2;
    #pragma unroll
    for (int j = 0; j < 4; j++)
        boff[j] = ((wn * 64 + (2 * j + (lane >> 4)) * 8 + (lane & 7)) * 36 +
                   (((lane >> 3) & 1) << 2)) << 2;

    float acc[2][8][4];
    #pragma unroll
    for (int i = 0; i < 2; i++)
        #pragma unroll
        for (int j = 0; j < 8; j++)
            #pragma unroll
            for (int q = 0; q < 4; q++) acc[i][j][q] = 0.f;

    const int NT = K / 32;

    {
        #pragma unroll
        for (int q = 0; q < 2; q++)
            cp16(sm + (ar + q * 32) * 36 + ac, A + (size_t)(m0 + ar + q * 32) * K + ac);
        #pragma unroll
        for (int q = 0; q < 8; q++)
            cp16(sm + 4608 + (ar + q * 32) * 36 + ac, W + (size_t)(ar + q * 32) * K + ac);
        asm volatile("cp.async.commit_group;\n");
    }

    #pragma unroll 1
    for (int kt = 0; kt < NT; ++kt) {
        int cur = kt & 1;
        if (kt + 1 < NT) {
            int k0 = (kt + 1) * 32;
            float* Ad = sm + (cur ^ 1) * 2304;
            float* Bd = sm + 4608 + (cur ^ 1) * 9216;
            #pragma unroll
            for (int q = 0; q < 2; q++)
                cp16(Ad + (ar + q * 32) * 36 + ac, A + (size_t)(m0 + ar + q * 32) * K + k0 + ac);
            #pragma unroll
            for (int q = 0; q < 8; q++)
                cp16(Bd + (ar + q * 32) * 36 + ac, W + (size_t)(ar + q * 32) * K + k0 + ac);
            asm volatile("cp.async.commit_group;\n");
            asm volatile("cp.async.wait_group 1;\n");
        } else {
            asm volatile("cp.async.wait_group 0;\n");
        }
        __syncthreads();

        uint32_t abase = smem_u + cur * 9216;
        uint32_t bbase = smem_u + 18432 + cur * 36864;
        #pragma unroll
        for (int ks = 0; ks < 4; ks++) {
            uint32_t kkb = ks * 32;
            uint32_t a[2][4], b[8][2];
            ldsm4(a[0][0], a[0][1], a[0][2], a[0][3], abase + aoff[0] + kkb);
            ldsm4(a[1][0], a[1][1], a[1][2], a[1][3], abase + aoff[1] + kkb);
            ldsm4(b[0][0], b[0][1], b[1][0], b[1][1], bbase + boff[0] + kkb);
            ldsm4(b[2][0], b[2][1], b[3][0], b[3][1], bbase + boff[1] + kkb);
            ldsm4(b[4][0], b[4][1], b[5][0], b[5][1], bbase + boff[2] + kkb);
            ldsm4(b[6][0], b[6][1], b[7][0], b[7][1], bbase + boff[3] + kkb);
            #pragma unroll
            for (int mi = 0; mi < 2; mi++)
                #pragma unroll
                for (int nf = 0; nf < 8; nf++)
                    asm volatile(
                        "mma.sync.aligned.m16n8k8.row.col.f32.tf32.tf32.f32 "
                        "{%0,%1,%2,%3}, {%4,%5,%6,%7}, {%8,%9}, {%0,%1,%2,%3};"
                        : "+f"(acc[mi][nf][0]), "+f"(acc[mi][nf][1]),
                          "+f"(acc[mi][nf][2]), "+f"(acc[mi][nf][3])
                        : "r"(a[mi][0]), "r"(a[mi][1]), "r"(a[mi][2]), "r"(a[mi][3]),
                          "r"(b[nf][0]), "r"(b[nf][1]));
        }
        __syncthreads();
    }

    // -------- fused epilogue: row statistics over full 256-col rows --------
    float* s1 = sm;
    float* s2 = sm + 256;
    float* s3 = sm + 512;
    float* stg = sm + 1024;      // MODE 2 staging: [64][260]

    #pragma unroll
    for (int mi = 0; mi < 2; mi++) {
        #pragma unroll
        for (int h = 0; h < 2; h++) {
            float a1 = 0.f, a2 = 0.f;
            #pragma unroll
            for (int nf = 0; nf < 8; nf++) {
                #pragma unroll
                for (int q = 0; q < 2; q++) {
                    int n = wn * 64 + nf * 8 + tig * 2 + q;
                    float x = acc[mi][nf][h * 2 + q] + bias[n];
                    acc[mi][nf][h * 2 + q] = x;
                    a1 += x; a2 += x * x;
                }
            }
            a1 += __shfl_xor_sync(0xffffffffu, a1, 1);
            a1 += __shfl_xor_sync(0xffffffffu, a1, 2);
            a2 += __shfl_xor_sync(0xffffffffu, a2, 1);
            a2 += __shfl_xor_sync(0xffffffffu, a2, 2);
            if (tig == 0) {
                int rl = wm * 32 + mi * 16 + h * 8 + g;
                s1[wn * 64 + rl] = a1;
                s2[wn * 64 + rl] = a2;
            }
        }
    }
    __syncthreads();

    float mu2[2][2], rs2[2][2];
    #pragma unroll
    for (int mi = 0; mi < 2; mi++)
        #pragma unroll
        for (int h = 0; h < 2; h++) {
            int rl = wm * 32 + mi * 16 + h * 8 + g;
            float t1 = s1[rl] + s1[64 + rl] + s1[128 + rl] + s1[192 + rl];
            float t2 = s2[rl] + s2[64 + rl] + s2[128 + rl] + s2[192 + rl];
            float mu = t1 * (1.0f / 256.0f);
            float var = t2 * (1.0f / 256.0f) - mu * mu;
            mu2[mi][h] = mu;
            rs2[mi][h] = rsqrtf(var + 1e-5f);
        }

    #pragma unroll
    for (int mi = 0; mi < 2; mi++) {
        #pragma unroll
        for (int h = 0; h < 2; h++) {
            float a2 = 0.f;
            #pragma unroll
            for (int nf = 0; nf < 8; nf++) {
                #pragma unroll
                for (int q = 0; q < 2; q++) {
                    int n = wn * 64 + nf * 8 + tig * 2 + q;
                    float y = (acc[mi][nf][h * 2 + q] - mu2[mi][h]) * rs2[mi][h] * lw[n] + lb[n];
                    acc[mi][nf][h * 2 + q] = y;
                    a2 += y * y;
                }
            }
            if (MODE == 0) {
                a2 += __shfl_xor_sync(0xffffffffu, a2, 1);
                a2 += __shfl_xor_sync(0xffffffffu, a2, 2);
                if (tig == 0) {
                    int rl = wm * 32 + mi * 16 + h * 8 + g;
                    s3[wn * 64 + rl] = a2;
                }
            }
        }
    }

    float inv[2][2];
    if (MODE == 0) {
        __syncthreads();
        #pragma unroll
        for (int mi = 0; mi < 2; mi++)
            #pragma unroll
            for (int h = 0; h < 2; h++) {
                int rl = wm * 32 + mi * 16 + h * 8 + g;
                float nrm = sqrtf(s3[rl] + s3[64 + rl] + s3[128 + rl] + s3[192 + rl]);
                inv[mi][h] = 1.0f / fmaxf(nrm, 1e-4f);
            }
    }

    #pragma unroll
    for (int mi = 0; mi < 2; mi++) {
        #pragma unroll
        for (int nf = 0; nf < 8; nf++) {
            int n = wn * 64 + nf * 8 + tig * 2;
            #pragma unroll
            for (int h = 0; h < 2; h++) {
                int rl = wm * 32 + mi * 16 + h * 8 + g;
                int m = m0 + rl;
                float v0 = acc[mi][nf][h * 2 + 0];
                float v1 = acc[mi][nf][h * 2 + 1];
                if (MODE == 0) {
                    v0 *= inv[mi][h];
                    v1 *= inv[mi][h];
                } else {
                    float2 bs = *(const float2*)(base + (size_t)m * C1 + n);
                    v0 += bs.x;
                    v1 += bs.y;
                }
                if (MODE == 2) {
                    stg[rl * 260 + n] = v0;
                    stg[rl * 260 + n + 1] = v1;
                } else {
                    *(float2*)(out + (size_t)m * C1 + n) = make_float2(v0, v1);
                    if (MODE == 1 && out_tf)
                        *(float2*)(out_tf + (size_t)m * C1 + n) = make_float2(tfr(v0), tfr(v1));
                }
            }
        }
    }

    if (MODE == 2) {
        // write spatial layout: out[(b*C1+c)*LSEQ + l], l = m>>3, b = m&7
        __syncthreads();
        int l0 = blockIdx.x << 3;   // 8 l-positions per block, 8-aligned
        #pragma unroll
        for (int it = 0; it < 8; it++) {
            int idx = it * 256 + tid;        // 2048 (b,c) pairs
            int b = idx >> 8, c = idx & 255;
            float v[8];
            #pragma unroll
            for (int j = 0; j < 8; j++) v[j] = stg[(j * 8 + b) * 260 + c];
            float* dst = out + ((size_t)(b * C1 + c)) * LSEQ + l0;
            *(float4*)dst = make_float4(v[0], v[1], v[2], v[3]);
            *(float4*)(dst + 4) = make_float4(v[4], v[5], v[6], v[7]);
        }
    }
}

// ---------------- conv1x1 GEMM (128x128 tile): A from a4 [b,c2,l]; BN+pos epilogue ----------
__global__ void __launch_bounds__(256, 2) gemm_conv(
    const float* __restrict__ A4, const float* __restrict__ W,
    const float* __restrict__ bias, float* __restrict__ C,
    const float* __restrict__ e0, const float* __restrict__ e1,
    const float* __restrict__ ps, const float* __restrict__ pc) {
    const int K = C2;
    __shared__ uint32_t As[128 * 36];
    __shared__ uint32_t Bs[128 * 36];
    int tid = threadIdx.x;
    int m0 = blockIdx.x << 7, n0 = blockIdx.y << 7;
    int l0 = m0 >> 3;
    int warp = tid >> 5, lane = tid & 31;
    int wm = warp & 3, wn = warp >> 2;
    int g = lane >> 2, tig = lane & 3;

    int kk = tid >> 3, bb = tid & 7;
    int br = tid >> 3, bc = (tid & 7) << 2;

    uint32_t abase = (uint32_t)__cvta_generic_to_shared(As);
    uint32_t bbase = (uint32_t)__cvta_generic_to_shared(Bs);
    uint32_t aoff[2], boff[4];
    #pragma unroll
    for (int mi = 0; mi < 2; mi++)
        aoff[mi] = ((wm * 32 + mi * 16 + (lane & 15)) * 36 + ((lane >> 4) << 2)) << 2;
    #pragma unroll
    for (int j = 0; j < 4; j++)
        boff[j] = ((wn * 64 + (2 * j + (lane >> 4)) * 8 + (lane & 7)) * 36 +
                   (((lane >> 3) & 1) << 2)) << 2;

    float acc[2][8][4];
    #pragma unroll
    for (int i = 0; i < 2; i++)
        #pragma unroll
        for (int j = 0; j < 8; j++)
            #pragma unroll
            for (int q = 0; q < 4; q++) acc[i][j][q] = 0.f;

    for (int k0 = 0; k0 < K; k0 += 32) {
        const float* asrc = A4 + (size_t)(bb * C2 + k0 + kk) * LSEQ + l0;
        #pragma unroll
        for (int q = 0; q < 4; q++) {
            float4 v = *(const float4*)(asrc + q * 4);
            As[((q * 4 + 0) * 8 + bb) * 36 + kk] = f2tf(v.x);
            As[((q * 4 + 1) * 8 + bb) * 36 + kk] = f2tf(v.y);
            As[((q * 4 + 2) * 8 + bb) * 36 + kk] = f2tf(v.z);
            As[((q * 4 + 3) * 8 + bb) * 36 + kk] = f2tf(v.w);
        }
        #pragma unroll
        for (int q = 0; q < 4; q++) {
            float4 v = *(const float4*)(W + (size_t)(n0 + br + q * 32) * K + k0 + bc);
            uint4 u = make_uint4(__float_as_uint(v.x), __float_as_uint(v.y),
                                 __float_as_uint(v.z), __float_as_uint(v.w));
            *(uint4*)(Bs + (br + q * 32) * 36 + bc) = u;
        }
        __syncthreads();

        #pragma unroll
        for (int ks = 0; ks < 4; ks++) {
            uint32_t kkb = ks * 32;
            uint32_t a[2][4], b[8][2];
            ldsm4(a[0][0], a[0][1], a[0][2], a[0][3], abase + aoff[0] + kkb);
            ldsm4(a[1][0], a[1][1], a[1][2], a[1][3], abase + aoff[1] + kkb);
            ldsm4(b[0][0], b[0][1], b[1][0], b[1][1], bbase + boff[0] + kkb);
            ldsm4(b[2][0], b[2][1], b[3][0], b[3][1], bbase + boff[1] + kkb);
            ldsm4(b[4][0], b[4][1], b[5][0], b[5][1], bbase + boff[2] + kkb);
            ldsm4(b[6][0], b[6][1], b[7][0], b[7][1], bbase + boff[3] + kkb);
            #pragma unroll
            for (int mi = 0; mi < 2; mi++)
                #pragma unroll
                for (int nf = 0; nf < 8; nf++)
                    asm volatile(
                        "mma.sync.aligned.m16n8k8.row.col.f32.tf32.tf32.f32 "
                        "{%0,%1,%2,%3}, {%4,%5,%6,%7}, {%8,%9}, {%0,%1,%2,%3};"
                        : "+f"(acc[mi][nf][0]), "+f"(acc[mi][nf][1]),
                          "+f"(acc[mi][nf][2]), "+f"(acc[mi][nf][3])
                        : "r"(a[mi][0]), "r"(a[mi][1]), "r"(a[mi][2]), "r"(a[mi][3]),
                          "r"(b[nf][0]), "r"(b[nf][1]));
        }
        __syncthreads();
    }

    #pragma unroll
    for (int mi = 0; mi < 2; mi++) {
        #pragma unroll
        for (int nf = 0; nf < 8; nf++) {
            int n = n0 + wn * 64 + nf * 8 + tig * 2;
            int r0 = m0 + wm * 32 + mi * 16 + g;
            #pragma unroll
            for (int h = 0; h < 2; h++) {
                int m = r0 + h * 8;
                int l = m >> 3;
                float v0 = acc[mi][nf][h * 2 + 0] + bias[n];
                float v1 = acc[mi][nf][h * 2 + 1] + bias[n + 1];
                v0 = tfr(v0 * BNS * e0[n] + e1[n] + posv(ps, pc, l, n));
                v1 = tfr(v1 * BNS * e0[n + 1] + e1[n + 1] + posv(ps, pc, l, n + 1));
                *(float2*)(C + (size_t)m * C1 + n) = make_float2(v0, v1);
            }
        }
    }
}

// ---------------- cosFormer KV accumulation (partial over L/8 chunk) ----------------
__global__ void kv_partial_kernel(const float* __restrict__ Kn, const float* __restrict__ V,
                                  float* __restrict__ partial) {
    int head = blockIdx.y, chunk = blockIdx.x;
    int batch = head >> 3, hh = head & 7;
    int tid = threadIdx.x;
    int g = tid >> 5, m = tid & 31;
    __shared__ float sk[8][64];
    __shared__ float sv[8][32];
    float acc[8] = {};
    int l0 = chunk * 392;
    for (int lt = 0; lt < 392; lt += 8) {
        int l = l0 + lt + g;
        float wi = (float)(l + 1) * (1.0f / LSEQ);
        float sw, cw; sincosf(wi, &sw, &cw);
        int off = ((l << 3) + batch) * C1 + hh * HDIM + m;
        float kv_ = Kn[off];
        sk[g][m] = kv_ * cw;
        sk[g][32 + m] = kv_ * sw;
        sv[g][m] = V[off];
        __syncthreads();
        #pragma unroll
        for (int ll = 0; ll < 8; ll++) {
            float vvm = sv[ll][m];
            #pragma unroll
            for (int j = 0; j < 8; j++)
                acc[j] += sk[ll][g * 8 + j] * vvm;
        }
        __syncthreads();
    }
    #pragma unroll
    for (int j = 0; j < 8; j++)
        partial[((head * 8 + chunk) * 64 + (g * 8 + j)) * 32 + m] = acc[j];
}

// ---------------- attn = Q_ @ KV (KV reduced from partials in-load), RMSNorm ----------------
__global__ void attn_kernel(const float* __restrict__ Q, const float* __restrict__ partial,
                            const float* __restrict__ rms_w, float* __restrict__ attnOut) {
    int head = blockIdx.y, strip = blockIdx.x;
    int batch = head >> 3, hh = head & 7;
    int tid = threadIdx.x;
    __shared__ float skv[64][32];
    __shared__ float sq[8][32];
    __shared__ float srw[32];
    for (int i = tid; i < 2048; i += 256) {
        float s = 0.f;
        #pragma unroll
        for (int ch = 0; ch < 8; ch++) s += partial[(head * 8 + ch) * 2048 + i];
        skv[i >> 5][i & 31] = s;
    }
    if (tid < 32) srw[tid] = rms_w[tid];
    __syncthreads();
    int warp = tid >> 5, m = tid & 31;
    int lend = strip * 392 + 392;
    for (int lt = strip * 392; lt < lend; lt += 8) {
        int l = lt + warp;
        sq[warp][m] = Q[((l << 3) + batch) * C1 + hh * HDIM + m];
        __syncthreads();
        float wi = (float)(l + 1) * (1.0f / LSEQ);
        float sw, cw; sincosf(wi, &sw, &cw);
        float s1 = 0.f, s2 = 0.f;
        #pragma unroll
        for (int d = 0; d < 32; d++) {
            float q = sq[warp][d];
            s1 += q * skv[d][m];
            s2 += q * skv[32 + d][m];
        }
        float a = cw * s1 + sw * s2;
        float ss = a * a;
        #pragma unroll
        for (int o = 16; o; o >>= 1) ss += __shfl_xor_sync(0xffffffffu, ss, o);
        float r = rsqrtf(ss * (1.0f / 32.0f) + 1e-6f);
        attnOut[((l << 3) + batch) * C1 + hh * HDIM + m] = tfr(srw[m] * a * r);
        __syncthreads();
    }
}

// ---------------- bilinear x2 upsample, 4 outputs/thread ----------------
__device__ __forceinline__ float4 up4(const float* __restrict__ src, int y, int j) {
    int ih = y >> 1;
    int ra = (y & 1) ? ih : ih - 1;
    float wa = (y & 1) ? 0.75f : 0.25f;
    float wb = 1.0f - wa;
    int rb = min(ra + 1, 55);
    ra = max(ra, 0);
    const float* pa = src + ra * 56;
    const float* pb = src + rb * 56;
    int cm1 = max(2 * j - 1, 0);
    int c0 = 2 * j, c1 = 2 * j + 1;
    int c2 = min(2 * j + 2, 55);
    float fm1 = wa * pa[cm1] + wb * pb[cm1];
    float f0  = wa * pa[c0]  + wb * pb[c0];
    float f1  = wa * pa[c1]  + wb * pb[c1];
    float f2  = wa * pa[c2]  + wb * pb[c2];
    float4 o;
    o.x = 0.25f * fm1 + 0.75f * f0;
    o.y = 0.75f * f0 + 0.25f * f1;
    o.z = 0.25f * f0 + 0.75f * f1;
    o.w = 0.75f * f1 + 0.25f * f2;
    return o;
}

__global__ void up_a3_kernel(const float* __restrict__ sp, const float* __restrict__ a3,
                             float* __restrict__ outp) {
    int idx = blockIdx.x * 256 + threadIdx.x;       // 8*256*112*28 quads
    int j = idx % 28; int t = idx / 28; int y = t % 112; int bc = t / 112;
    float4 v = up4(sp + (size_t)bc * LSEQ, y, j);
    size_t o = ((size_t)bc * 112 + y) * 112 + 4 * j;
    float4 m = *(const float4*)(a3 + o);
    v.x *= m.x; v.y *= m.y; v.z *= m.z; v.w *= m.w;
    *(float4*)(outp + o) = v;
}

__global__ void up_a4_kernel(const float* __restrict__ a4, float* __restrict__ outp) {
    int idx = blockIdx.x * 256 + threadIdx.x;       // 8*512*112*28 quads
    int j = idx % 28; int t = idx / 28; int y = t % 112; int bc = t / 112;
    float4 v = up4(a4 + (size_t)bc * LSEQ, y, j);
    *(float4*)(outp + ((size_t)bc * 112 + y) * 112 + 4 * j) = v;
}

// ---------------- launch ----------------
extern "C" void kernel_launch(void* const* d_in, const int* in_sizes, int n_in,
                              void* d_out, int out_size) {
    const float* a3     = (const float*)d_in[0];
    const float* a4     = (const float*)d_in[1];
    const float* conv_w = (const float*)d_in[2];
    const float* conv_b = (const float*)d_in[3];
    const float* bn_w   = (const float*)d_in[4];
    const float* bn_b   = (const float*)d_in[5];
    const float* q_w    = (const float*)d_in[6];
    const float* q_b    = (const float*)d_in[7];
    const float* q_ln_w = (const float*)d_in[8];
    const float* q_ln_b = (const float*)d_in[9];
    const float* k_w    = (const float*)d_in[10];
    const float* k_b    = (const float*)d_in[11];
    const float* k_ln_w = (const float*)d_in[12];
    const float* k_ln_b = (const float*)d_in[13];
    const float* v_w    = (const float*)d_in[14];
    const float* v_b    = (const float*)d_in[15];
    const float* o_w    = (const float*)d_in[16];
    const float* o_b    = (const float*)d_in[17];
    const float* rms_w  = (const float*)d_in[18];
    const float* l1_w   = (const float*)d_in[19];
    const float* l1_b   = (const float*)d_in[20];
    const float* l2_w   = (const float*)d_in[21];
    const float* l2_b   = (const float*)d_in[22];
    const float* n1_w   = (const float*)d_in[23];
    const float* n1_b   = (const float*)d_in[24];
    const float* n2_w   = (const float*)d_in[25];
    const float* n2_b   = (const float*)d_in[26];
    float* out = (float*)d_out;

    float *p_res, *p_X3, *p_X4, *p_Q, *p_K, *p_V;
    float *p_attn, *p_out1, *p_out1tf, *p_sp, *p_H, *p_part, *p_ps, *p_pc;
    float *p_wc, *p_wq, *p_wk, *p_wv, *p_wo, *p_wl1, *p_wl2;
    cudaGetSymbolAddress((void**)&p_res, g_res);
    cudaGetSymbolAddress((void**)&p_X3, g_X3);
    cudaGetSymbolAddress((void**)&p_X4, g_X4);
    cudaGetSymbolAddress((void**)&p_Q, g_Q);
    cudaGetSymbolAddress((void**)&p_K, g_K);
    cudaGetSymbolAddress((void**)&p_V, g_V);
    cudaGetSymbolAddress((void**)&p_attn, g_attn);
    cudaGetSymbolAddress((void**)&p_out1, g_out1);
    cudaGetSymbolAddress((void**)&p_out1tf, g_out1tf);
    cudaGetSymbolAddress((void**)&p_sp, g_sp);
    cudaGetSymbolAddress((void**)&p_H, g_H);
    cudaGetSymbolAddress((void**)&p_part, g_part);
    cudaGetSymbolAddress((void**)&p_ps, g_psin);
    cudaGetSymbolAddress((void**)&p_pc, g_pcos);
    cudaGetSymbolAddress((void**)&p_wc, g_wc);
    cudaGetSymbolAddress((void**)&p_wq, g_wq);
    cudaGetSymbolAddress((void**)&p_wk, g_wk);
    cudaGetSymbolAddress((void**)&p_wv, g_wv);
    cudaGetSymbolAddress((void**)&p_wo, g_wo);
    cudaGetSymbolAddress((void**)&p_wl1, g_wl1);
    cudaGetSymbolAddress((void**)&p_wl2, g_wl2);

    // exactly 3 side streams (stream creation allocates driver memory; 3 passed the
    // harness mem checkpoint in prior rounds, 5 did not)
    static cudaStream_t sW = 0, sU = 0, sQ = 0;
    static cudaEvent_t evRoot = 0, evW = 0, evU = 0, evQ = 0, evP = 0, evC = 0, evV = 0;
    if (sW == 0) {
        cudaStreamCreateWithFlags(&sW, cudaStreamNonBlocking);
        cudaStreamCreateWithFlags(&sU, cudaStreamNonBlocking);
        cudaStreamCreateWithFlags(&sQ, cudaStreamNonBlocking);
        cudaEventCreateWithFlags(&evRoot, cudaEventDisableTiming);
        cudaEventCreateWithFlags(&evW, cudaEventDisableTiming);
        cudaEventCreateWithFlags(&evU, cudaEventDisableTiming);
        cudaEventCreateWithFlags(&evQ, cudaEventDisableTiming);
        cudaEventCreateWithFlags(&evP, cudaEventDisableTiming);
        cudaEventCreateWithFlags(&evC, cudaEventDisableTiming);
        cudaEventCreateWithFlags(&evV, cudaEventDisableTiming);
    }

    const int SMEM_CA = (2 * 128 * 36 + 2 * 128 * 36) * 4;   // 73728 bytes
    const int SMEM_LN = (2 * 64 * 36 + 2 * 256 * 36) * 4;    // 92160 bytes
    cudaFuncSetAttribute(gemm_ca<256, 0>, cudaFuncAttributeMaxDynamicSharedMemorySize, SMEM_CA);
    cudaFuncSetAttribute(gemm_ca<256, 1>, cudaFuncAttributeMaxDynamicSharedMemorySize, SMEM_CA);
    cudaFuncSetAttribute(gemm_ln<256, 0>, cudaFuncAttributeMaxDynamicSharedMemorySize, SMEM_LN);
    cudaFuncSetAttribute(gemm_ln<256, 1>, cudaFuncAttributeMaxDynamicSharedMemorySize, SMEM_LN);
    cudaFuncSetAttribute(gemm_ln<1024, 2>, cudaFuncAttributeMaxDynamicSharedMemorySize, SMEM_LN);

    dim3 b328(32, 8);

    // ---- fork side streams from the capture-origin (legacy) stream ----
    cudaEventRecord(evRoot, 0);
    cudaStreamWaitEvent(sW, evRoot, 0);
    cudaStreamWaitEvent(sU, evRoot, 0);
    cudaStreamWaitEvent(sQ, evRoot, 0);

    // sW: all weight tf32 conversions in one launch
    tfconv_all<<<896, 256, 0, sW>>>(conv_w, q_w, k_w, v_w, o_w, l1_w, l2_w,
                                    p_wc, p_wq, p_wk, p_wv, p_wo, p_wl1, p_wl2);
    cudaEventRecord(evW, sW);

    // sU: a4 bilinear upsample first (independent), V projection appended below
    up_a4_kernel<<<50176, 256, 0, sU>>>(a4, out + 25690112);
    cudaEventRecord(evU, sU);

    // sQ: pos tables + a3 pool/transpose, then fused Q projection
    pos_small_kernel<<<14, 256, 0, sQ>>>(p_ps, p_pc);
    pool_transpose_tokens<<<dim3(98, 8, 8), b328, 0, sQ>>>(a3, p_res, p_X3, p_ps, p_pc);
    cudaEventRecord(evP, sQ);
    cudaStreamWaitEvent(sQ, evW, 0);
    gemm_ln<256, 0><<<392, 256, SMEM_LN, sQ>>>(p_X3, p_wq, q_b, q_ln_w, q_ln_b,
                                               nullptr, p_Q, nullptr);
    cudaEventRecord(evQ, sQ);

    // main: conv1x1 + BN + pos -> X4 (needs weights + pos tables from sQ)
    cudaStreamWaitEvent(0, evW, 0);
    cudaStreamWaitEvent(0, evP, 0);
    gemm_conv<<<dim3(196, 2), 256>>>(a4, p_wc, conv_b, p_X4, bn_w, bn_b, p_ps, p_pc);
    cudaEventRecord(evC, 0);

    // sU: V projection (needs X4) — overlaps K gemm_ln on main
    cudaStreamWaitEvent(sU, evC, 0);
    gemm_ca<256, 0><<<dim3(196, 2), 256, SMEM_CA, sU>>>(p_X4, p_wv, v_b, p_V, C1);
    cudaEventRecord(evV, sU);

    // main: fused K projection + LN + L2
    gemm_ln<256, 0><<<392, 256, SMEM_LN>>>(p_X4, p_wk, k_b, k_ln_w, k_ln_b,
                                           nullptr, p_K, nullptr);

    // linear attention
    cudaStreamWaitEvent(0, evV, 0);
    kv_partial_kernel<<<dim3(8, 64), 256>>>(p_K, p_V, p_part);
    cudaStreamWaitEvent(0, evQ, 0);
    attn_kernel<<<dim3(8, 64), 256>>>(p_Q, p_part, rms_w, p_attn);

    // output projection + residual + LN (fused; res from sQ ordered via evQ)
    gemm_ln<256, 1><<<392, 256, SMEM_LN>>>(p_attn, p_wo, o_b, n1_w, n1_b,
                                           p_res, p_out1, p_out1tf);

    // FFN: up+GELU, then down + residual + LN, writing SPATIAL layout directly
    gemm_ca<256, 1><<<dim3(196, 8), 256, SMEM_CA>>>(p_out1tf, p_wl1, l1_b, p_H, 1024);
    gemm_ln<1024, 2><<<392, 256, SMEM_LN>>>(p_H, p_wl2, l2_b, n2_w, n2_b,
                                            p_out1, p_sp, nullptr);

    // outputs (transpose eliminated — FFN2 wrote g_sp directly)
    up_a3_kernel<<<25088, 256>>>(p_sp, a3, out);

    // join the a4-upsample branch
    cudaStreamWaitEvent(0, evU, 0);
}

// round 16
// speedup vs baseline: 1.0451x; 1.0451x over previous
#include <cuda_runtime.h>
#include <cuda_bf16.h>
#include <cstdint>
#include <math.h>

// ---------------- constants ----------------
#define LSEQ   3136        // 56*56
#define BATCH  8
#define TOK    25088       // LSEQ*BATCH
#define C1     256
#define C2     512
#define NHEAD  8
#define HDIM   32
#define BNS    0.9999950000374997f   // 1/sqrt(1+1e-5)
#define MHALF  12544       // TOK/2 row split for tail pipelining

// ---------------- scratch (device globals; no allocation) ----------------
__device__ float g_res[TOK * C1];          // residual tokens [t,c]
__device__ float g_X3[TOK * C1];           // res + pos (tf32-rounded)
__device__ float g_X4[TOK * C1];           // conv/bn + pos (tf32-rounded)
__device__ float g_Q[TOK * C1];
__device__ float g_K[TOK * C1];
__device__ float g_V[TOK * C1];
__device__ float g_attn[TOK * C1];         // tf32-rounded
__device__ float g_out1[TOK * C1];
__device__ float g_out1tf[TOK * C1];       // tf32-rounded copy for FFN1
__device__ float g_out2[TOK * C1];
__device__ float g_sp[BATCH * C1 * LSEQ];  // out2 in [b,c,l] layout
__device__ float g_H[TOK * 1024];          // FFN hidden (tf32-rounded)
__device__ float g_part[64 * 8 * 64 * 32]; // partial KV
__device__ float g_psin[56 * 64];          // sin(r * omega_k)
__device__ float g_pcos[56 * 64];          // cos(r * omega_k)
// tf32-converted weights
__device__ float g_wc[C1 * C2];
__device__ float g_wq[C1 * C1];
__device__ float g_wk[C1 * C1];
__device__ float g_wv[C1 * C1];
__device__ float g_wo[C1 * C1];
__device__ float g_wl1[4 * C1 * C1];
__device__ float g_wl2[4 * C1 * C1];

// ---------------- helpers ----------------
__device__ __forceinline__ uint32_t f2tf(float f) {
    uint32_t u;
    asm("cvt.rna.tf32.f32 %0, %1;" : "=r"(u) : "f"(f));
    return u;
}
__device__ __forceinline__ float tfr(float f) { return __uint_as_float(f2tf(f)); }

__device__ __forceinline__ void cp16(void* dst_smem, const void* src) {
    uint32_t d = (uint32_t)__cvta_generic_to_shared(dst_smem);
    asm volatile("cp.async.cg.shared.global [%0], [%1], 16;\n" :: "r"(d), "l"(src));
}

__device__ __forceinline__ void ldsm4(uint32_t& r0, uint32_t& r1, uint32_t& r2, uint32_t& r3,
                                      uint32_t addr) {
    asm volatile("ldmatrix.sync.aligned.m8n8.x4.shared.b16 {%0,%1,%2,%3}, [%4];"
                 : "=r"(r0), "=r"(r1), "=r"(r2), "=r"(r3) : "r"(addr));
}

// small sincos tables: 56 positions x 64 frequencies
__global__ void pos_small_kernel(float* __restrict__ ps, float* __restrict__ pc) {
    int idx = blockIdx.x * 256 + threadIdx.x;   // 3584
    if (idx < 3584) {
        int r = idx >> 6, k = idx & 63;
        float om = expf(-(float)k * 0.14391156716f);   // ln(10000)/64
        float sv, cv;
        sincosf((float)r * om, &sv, &cv);
        ps[idx] = sv;
        pc[idx] = cv;
    }
}

__device__ __forceinline__ float posv(const float* __restrict__ ps, const float* __restrict__ pc,
                                      int l, int c) {
    int row = l / 56, col = l - row * 56;
    int k = c & 63;
    int rr = (c < 128) ? row : col;
    return (c & 64) ? pc[rr * 64 + k] : ps[rr * 64 + k];
}

// one merged tf32 conversion over all 7 weight tensors (float4 granules)
__global__ void tfconv_all(const float* __restrict__ wc, const float* __restrict__ wq,
                           const float* __restrict__ wk, const float* __restrict__ wv,
                           const float* __restrict__ wo, const float* __restrict__ wl1,
                           const float* __restrict__ wl2,
                           float* __restrict__ oc, float* __restrict__ oq,
                           float* __restrict__ ok, float* __restrict__ ov,
                           float* __restrict__ oo, float* __restrict__ ol1,
                           float* __restrict__ ol2) {
    int q = blockIdx.x * 256 + threadIdx.x;   // 229376 total
    const float* src; float* dst; int off;
    if (q < 32768)       { src = wc;  dst = oc;  off = q; }
    else if (q < 49152)  { src = wq;  dst = oq;  off = q - 32768; }
    else if (q < 65536)  { src = wk;  dst = ok;  off = q - 49152; }
    else if (q < 81920)  { src = wv;  dst = ov;  off = q - 65536; }
    else if (q < 98304)  { src = wo;  dst = oo;  off = q - 81920; }
    else if (q < 163840) { src = wl1; dst = ol1; off = q - 98304; }
    else                 { src = wl2; dst = ol2; off = q - 163840; }
    float4 v = *(const float4*)(src + off * 4);
    v.x = tfr(v.x); v.y = tfr(v.y); v.z = tfr(v.z); v.w = tfr(v.w);
    *(float4*)(dst + off * 4) = v;
}

// ---------------- fused pool(2x2) + transpose + pos: a3 -> res, X3 ----------------
__global__ void pool_transpose_tokens(const float* __restrict__ a3,
                                      float* __restrict__ res, float* __restrict__ X3,
                                      const float* __restrict__ ps, const float* __restrict__ pc) {
    __shared__ float s[32][33];
    int l0 = blockIdx.x << 5, c0 = blockIdx.y << 5, batch = blockIdx.z;
    int tx = threadIdx.x, ty = threadIdx.y;
    #pragma unroll
    for (int k = 0; k < 4; k++) {
        int c = c0 + ty + k * 8;
        int l = l0 + tx;
        int ly = l / 56, lx = l - ly * 56;
        const float* p = a3 + ((size_t)(batch * C1 + c) * 112 + 2 * ly) * 112 + 2 * lx;
        s[ty + k * 8][tx] = 0.25f * (p[0] + p[1] + p[112] + p[113]);
    }
    __syncthreads();
    #pragma unroll
    for (int k = 0; k < 4; k++) {
        int l = l0 + ty + k * 8, c = c0 + tx;
        float v = s[tx][ty + k * 8];
        int o = ((l << 3) + batch) * C1 + c;
        res[o] = v;
        X3[o] = tfr(v + posv(ps, pc, l, c));
    }
}

// ---------------- transpose tokens [t,256] -> [b,256,L], with l-offset for halves ----------
__global__ void transpose_to_spatial(const float* __restrict__ in, float* __restrict__ out,
                                     int loff) {
    __shared__ float s[32][33];
    int l0 = (blockIdx.x + loff) << 5, c0 = blockIdx.y << 5, batch = blockIdx.z;
    int tx = threadIdx.x, ty = threadIdx.y;
    #pragma unroll
    for (int k = 0; k < 4; k++)
        s[ty + k * 8][tx] = in[(((l0 + ty + k * 8) << 3) + batch) * C1 + c0 + tx];
    __syncthreads();
    #pragma unroll
    for (int k = 0; k < 4; k++)
        out[(batch * C1 + c0 + ty + k * 8) * LSEQ + l0 + tx] = s[tx][ty + k * 8];
}

// ---------------- TF32 GEMM, 128x128 tile (generic, row-independent epilogues) ----------
// EPI: 0 = bias, 1 = bias+GELU(exact)+tf32-round (FFN hidden)
template<int K, int EPI>
__global__ void __launch_bounds__(256, 2) gemm_ca(
    const float* __restrict__ A, const float* __restrict__ W,
    const float* __restrict__ bias, float* __restrict__ C, int N) {
    extern __shared__ float sm[];
    float* AsB = sm;             // [2][128*36]
    float* BsB = sm + 2 * 4608;  // [2][128*36]
    int tid = threadIdx.x;
    int m0 = blockIdx.x << 7, n0 = blockIdx.y << 7;
    int warp = tid >> 5, lane = tid & 31;
    int wm = warp & 3, wn = warp >> 2;
    int g = lane >> 2, tig = lane & 3;

    int ar = tid >> 3, ac = (tid & 7) << 2;

    uint32_t smem_u = (uint32_t)__cvta_generic_to_shared(sm);
    uint32_t aoff[2], boff[4];
    #pragma unroll
    for (int mi = 0; mi < 2; mi++)
        aoff[mi] = ((wm * 32 + mi * 16 + (lane & 15)) * 36 + ((lane >> 4) << 2)) << 2;
    #pragma unroll
    for (int j = 0; j < 4; j++)
        boff[j] = (((wn * 64 + (2 * j + (lane >> 4)) * 8 + (lane & 7)) * 36 +
                    (((lane >> 3) & 1) << 2)) << 2) + 36864;

    float acc[2][8][4];
    #pragma unroll
    for (int i = 0; i < 2; i++)
        #pragma unroll
        for (int j = 0; j < 8; j++)
            #pragma unroll
            for (int q = 0; q < 4; q++) acc[i][j][q] = 0.f;

    const int NT = K / 32;

    {
        #pragma unroll
        for (int q = 0; q < 4; q++)
            cp16(AsB + (ar + q * 32) * 36 + ac, A + (size_t)(m0 + ar + q * 32) * K + ac);
        #pragma unroll
        for (int q = 0; q < 4; q++)
            cp16(BsB + (ar + q * 32) * 36 + ac, W + (size_t)(n0 + ar + q * 32) * K + ac);
        asm volatile("cp.async.commit_group;\n");
    }

    #pragma unroll 1
    for (int kt = 0; kt < NT; ++kt) {
        int cur = kt & 1;
        if (kt + 1 < NT) {
            int k0 = (kt + 1) * 32;
            float* Ad = AsB + (cur ^ 1) * 4608;
            float* Bd = BsB + (cur ^ 1) * 4608;
            #pragma unroll
            for (int q = 0; q < 4; q++)
                cp16(Ad + (ar + q * 32) * 36 + ac, A + (size_t)(m0 + ar + q * 32) * K + k0 + ac);
            #pragma unroll
            for (int q = 0; q < 4; q++)
                cp16(Bd + (ar + q * 32) * 36 + ac, W + (size_t)(n0 + ar + q * 32) * K + k0 + ac);
            asm volatile("cp.async.commit_group;\n");
            asm volatile("cp.async.wait_group 1;\n");
        } else {
            asm volatile("cp.async.wait_group 0;\n");
        }
        __syncthreads();

        uint32_t abase = smem_u + cur * 18432;
        uint32_t bbase = smem_u + cur * 18432;
        #pragma unroll
        for (int ks = 0; ks < 4; ks++) {
            uint32_t kkb = ks * 32;
            uint32_t a[2][4], b[8][2];
            ldsm4(a[0][0], a[0][1], a[0][2], a[0][3], abase + aoff[0] + kkb);
            ldsm4(a[1][0], a[1][1], a[1][2], a[1][3], abase + aoff[1] + kkb);
            ldsm4(b[0][0], b[0][1], b[1][0], b[1][1], bbase + boff[0] + kkb);
            ldsm4(b[2][0], b[2][1], b[3][0], b[3][1], bbase + boff[1] + kkb);
            ldsm4(b[4][0], b[4][1], b[5][0], b[5][1], bbase + boff[2] + kkb);
            ldsm4(b[6][0], b[6][1], b[7][0], b[7][1], bbase + boff[3] + kkb);
            #pragma unroll
            for (int mi = 0; mi < 2; mi++)
                #pragma unroll
                for (int nf = 0; nf < 8; nf++)
                    asm volatile(
                        "mma.sync.aligned.m16n8k8.row.col.f32.tf32.tf32.f32 "
                        "{%0,%1,%2,%3}, {%4,%5,%6,%7}, {%8,%9}, {%0,%1,%2,%3};"
                        : "+f"(acc[mi][nf][0]), "+f"(acc[mi][nf][1]),
                          "+f"(acc[mi][nf][2]), "+f"(acc[mi][nf][3])
                        : "r"(a[mi][0]), "r"(a[mi][1]), "r"(a[mi][2]), "r"(a[mi][3]),
                          "r"(b[nf][0]), "r"(b[nf][1]));
        }
        __syncthreads();
    }

    #pragma unroll
    for (int mi = 0; mi < 2; mi++) {
        #pragma unroll
        for (int nf = 0; nf < 8; nf++) {
            int n = n0 + wn * 64 + nf * 8 + tig * 2;
            int r0 = m0 + wm * 32 + mi * 16 + g;
            #pragma unroll
            for (int h = 0; h < 2; h++) {
                int m = r0 + h * 8;
                float v0 = acc[mi][nf][h * 2 + 0] + bias[n];
                float v1 = acc[mi][nf][h * 2 + 1] + bias[n + 1];
                if (EPI == 1) {
                    v0 = tfr(0.5f * v0 * (1.0f + erff(v0 * 0.70710678118654752f)));
                    v1 = tfr(0.5f * v1 * (1.0f + erff(v1 * 0.70710678118654752f)));
                }
                *(float2*)(C + (size_t)m * N + n) = make_float2(v0, v1);
            }
        }
    }
}

// ---------------- TF32 GEMM, 64x256 tile with fused row-norm epilogue ----------------
// MODE 0: out = L2norm(LayerNorm(acc+bias; lw,lb))               (Q/K projection)
// MODE 1: out = base + LayerNorm(acc+bias; lw,lb); opt out_tf    (O-proj / FFN2)
template<int K, int MODE>
__global__ void __launch_bounds__(256, 2) gemm_ln(
    const float* __restrict__ A, const float* __restrict__ W,
    const float* __restrict__ bias, const float* __restrict__ lw,
    const float* __restrict__ lb, const float* __restrict__ base,
    float* __restrict__ out, float* __restrict__ out_tf) {
    extern __shared__ float sm[];
    int tid = threadIdx.x;
    int m0 = blockIdx.x << 6;
    int warp = tid >> 5, lane = tid & 31;
    int wm = warp & 1, wn = warp >> 1;
    int g = lane >> 2, tig = lane & 3;

    int ar = tid >> 3, ac = (tid & 7) << 2;

    uint32_t smem_u = (uint32_t)__cvta_generic_to_shared(sm);
    uint32_t aoff[2], boff[4];
    #pragma unroll
    for (int mi = 0; mi < 2; mi++)
        aoff[mi] = ((wm * 32 + mi * 16 + (lane & 15)) * 36 + ((lane >> 4) << 2)) << 2;
    #pragma unroll
    for (int j = 0; j < 4; j++)
        boff[j] = ((wn * 64 + (2 * j + (lane >> 4)) * 8 + (lane & 7)) * 36 +
                   (((lane >> 3) & 1) << 2)) << 2;

    float acc[2][8][4];
    #pragma unroll
    for (int i = 0; i < 2; i++)
        #pragma unroll
        for (int j = 0; j < 8; j++)
            #pragma unroll
            for (int q = 0; q < 4; q++) acc[i][j][q] = 0.f;

    const int NT = K / 32;

    {
        #pragma unroll
        for (int q = 0; q < 2; q++)
            cp16(sm + (ar + q * 32) * 36 + ac, A + (size_t)(m0 + ar + q * 32) * K + ac);
        #pragma unroll
        for (int q = 0; q < 8; q++)
            cp16(sm + 4608 + (ar + q * 32) * 36 + ac, W + (size_t)(ar + q * 32) * K + ac);
        asm volatile("cp.async.commit_group;\n");
    }

    #pragma unroll 1
    for (int kt = 0; kt < NT; ++kt) {
        int cur = kt & 1;
        if (kt + 1 < NT) {
            int k0 = (kt + 1) * 32;
            float* Ad = sm + (cur ^ 1) * 2304;
            float* Bd = sm + 4608 + (cur ^ 1) * 9216;
            #pragma unroll
            for (int q = 0; q < 2; q++)
                cp16(Ad + (ar + q * 32) * 36 + ac, A + (size_t)(m0 + ar + q * 32) * K + k0 + ac);
            #pragma unroll
            for (int q = 0; q < 8; q++)
                cp16(Bd + (ar + q * 32) * 36 + ac, W + (size_t)(ar + q * 32) * K + k0 + ac);
            asm volatile("cp.async.commit_group;\n");
            asm volatile("cp.async.wait_group 1;\n");
        } else {
            asm volatile("cp.async.wait_group 0;\n");
        }
        __syncthreads();

        uint32_t abase = smem_u + cur * 9216;
        uint32_t bbase = smem_u + 18432 + cur * 36864;
        #pragma unroll
        for (int ks = 0; ks < 4; ks++) {
            uint32_t kkb = ks * 32;
            uint32_t a[2][4], b[8][2];
            ldsm4(a[0][0], a[0][1], a[0][2], a[0][3], abase + aoff[0] + kkb);
            ldsm4(a[1][0], a[1][1], a[1][2], a[1][3], abase + aoff[1] + kkb);
            ldsm4(b[0][0], b[0][1], b[1][0], b[1][1], bbase + boff[0] + kkb);
            ldsm4(b[2][0], b[2][1], b[3][0], b[3][1], bbase + boff[1] + kkb);
            ldsm4(b[4][0], b[4][1], b[5][0], b[5][1], bbase + boff[2] + kkb);
            ldsm4(b[6][0], b[6][1], b[7][0], b[7][1], bbase + boff[3] + kkb);
            #pragma unroll
            for (int mi = 0; mi < 2; mi++)
                #pragma unroll
                for (int nf = 0; nf < 8; nf++)
                    asm volatile(
                        "mma.sync.aligned.m16n8k8.row.col.f32.tf32.tf32.f32 "
                        "{%0,%1,%2,%3}, {%4,%5,%6,%7}, {%8,%9}, {%0,%1,%2,%3};"
                        : "+f"(acc[mi][nf][0]), "+f"(acc[mi][nf][1]),
                          "+f"(acc[mi][nf][2]), "+f"(acc[mi][nf][3])
                        : "r"(a[mi][0]), "r"(a[mi][1]), "r"(a[mi][2]), "r"(a[mi][3]),
                          "r"(b[nf][0]), "r"(b[nf][1]));
        }
        __syncthreads();
    }

    // -------- fused epilogue: row statistics over full 256-col rows --------
    float* s1 = sm;
    float* s2 = sm + 256;
    float* s3 = sm + 512;

    #pragma unroll
    for (int mi = 0; mi < 2; mi++) {
        #pragma unroll
        for (int h = 0; h < 2; h++) {
            float a1 = 0.f, a2 = 0.f;
            #pragma unroll
            for (int nf = 0; nf < 8; nf++) {
                #pragma unroll
                for (int q = 0; q < 2; q++) {
                    int n = wn * 64 + nf * 8 + tig * 2 + q;
                    float x = acc[mi][nf][h * 2 + q] + bias[n];
                    acc[mi][nf][h * 2 + q] = x;
                    a1 += x; a2 += x * x;
                }
            }
            a1 += __shfl_xor_sync(0xffffffffu, a1, 1);
            a1 += __shfl_xor_sync(0xffffffffu, a1, 2);
            a2 += __shfl_xor_sync(0xffffffffu, a2, 1);
            a2 += __shfl_xor_sync(0xffffffffu, a2, 2);
            if (tig == 0) {
                int rl = wm * 32 + mi * 16 + h * 8 + g;
                s1[wn * 64 + rl] = a1;
                s2[wn * 64 + rl] = a2;
            }
        }
    }
    __syncthreads();

    float mu2[2][2], rs2[2][2];
    #pragma unroll
    for (int mi = 0; mi < 2; mi++)
        #pragma unroll
        for (int h = 0; h < 2; h++) {
            int rl = wm * 32 + mi * 16 + h * 8 + g;
            float t1 = s1[rl] + s1[64 + rl] + s1[128 + rl] + s1[192 + rl];
            float t2 = s2[rl] + s2[64 + rl] + s2[128 + rl] + s2[192 + rl];
            float mu = t1 * (1.0f / 256.0f);
            float var = t2 * (1.0f / 256.0f) - mu * mu;
            mu2[mi][h] = mu;
            rs2[mi][h] = rsqrtf(var + 1e-5f);
        }

    #pragma unroll
    for (int mi = 0; mi < 2; mi++) {
        #pragma unroll
        for (int h = 0; h < 2; h++) {
            float a2 = 0.f;
            #pragma unroll
            for (int nf = 0; nf < 8; nf++) {
                #pragma unroll
                for (int q = 0; q < 2; q++) {
                    int n = wn * 64 + nf * 8 + tig * 2 + q;
                    float y = (acc[mi][nf][h * 2 + q] - mu2[mi][h]) * rs2[mi][h] * lw[n] + lb[n];
                    acc[mi][nf][h * 2 + q] = y;
                    a2 += y * y;
                }
            }
            if (MODE == 0) {
                a2 += __shfl_xor_sync(0xffffffffu, a2, 1);
                a2 += __shfl_xor_sync(0xffffffffu, a2, 2);
                if (tig == 0) {
                    int rl = wm * 32 + mi * 16 + h * 8 + g;
                    s3[wn * 64 + rl] = a2;
                }
            }
        }
    }

    float inv[2][2];
    if (MODE == 0) {
        __syncthreads();
        #pragma unroll
        for (int mi = 0; mi < 2; mi++)
            #pragma unroll
            for (int h = 0; h < 2; h++) {
                int rl = wm * 32 + mi * 16 + h * 8 + g;
                float nrm = sqrtf(s3[rl] + s3[64 + rl] + s3[128 + rl] + s3[192 + rl]);
                inv[mi][h] = 1.0f / fmaxf(nrm, 1e-4f);
            }
    }

    #pragma unroll
    for (int mi = 0; mi < 2; mi++) {
        #pragma unroll
        for (int nf = 0; nf < 8; nf++) {
            int n = wn * 64 + nf * 8 + tig * 2;
            #pragma unroll
            for (int h = 0; h < 2; h++) {
                int m = m0 + wm * 32 + mi * 16 + h * 8 + g;
                float v0 = acc[mi][nf][h * 2 + 0];
                float v1 = acc[mi][nf][h * 2 + 1];
                if (MODE == 0) {
                    v0 *= inv[mi][h];
                    v1 *= inv[mi][h];
                } else {
                    float2 bs = *(const float2*)(base + (size_t)m * C1 + n);
                    v0 += bs.x;
                    v1 += bs.y;
                }
                *(float2*)(out + (size_t)m * C1 + n) = make_float2(v0, v1);
                if (MODE == 1 && out_tf)
                    *(float2*)(out_tf + (size_t)m * C1 + n) = make_float2(tfr(v0), tfr(v1));
            }
        }
    }
}

// ---------------- conv1x1 GEMM (128x128 tile): A from a4 [b,c2,l]; BN+pos epilogue ----------
__global__ void __launch_bounds__(256, 2) gemm_conv(
    const float* __restrict__ A4, const float* __restrict__ W,
    const float* __restrict__ bias, float* __restrict__ C,
    const float* __restrict__ e0, const float* __restrict__ e1,
    const float* __restrict__ ps, const float* __restrict__ pc) {
    const int K = C2;
    __shared__ uint32_t As[128 * 36];
    __shared__ uint32_t Bs[128 * 36];
    int tid = threadIdx.x;
    int m0 = blockIdx.x << 7, n0 = blockIdx.y << 7;
    int l0 = m0 >> 3;
    int warp = tid >> 5, lane = tid & 31;
    int wm = warp & 3, wn = warp >> 2;
    int g = lane >> 2, tig = lane & 3;

    int kk = tid >> 3, bb = tid & 7;
    int br = tid >> 3, bc = (tid & 7) << 2;

    uint32_t abase = (uint32_t)__cvta_generic_to_shared(As);
    uint32_t bbase = (uint32_t)__cvta_generic_to_shared(Bs);
    uint32_t aoff[2], boff[4];
    #pragma unroll
    for (int mi = 0; mi < 2; mi++)
        aoff[mi] = ((wm * 32 + mi * 16 + (lane & 15)) * 36 + ((lane >> 4) << 2)) << 2;
    #pragma unroll
    for (int j = 0; j < 4; j++)
        boff[j] = ((wn * 64 + (2 * j + (lane >> 4)) * 8 + (lane & 7)) * 36 +
                   (((lane >> 3) & 1) << 2)) << 2;

    float acc[2][8][4];
    #pragma unroll
    for (int i = 0; i < 2; i++)
        #pragma unroll
        for (int j = 0; j < 8; j++)
            #pragma unroll
            for (int q = 0; q < 4; q++) acc[i][j][q] = 0.f;

    for (int k0 = 0; k0 < K; k0 += 32) {
        const float* asrc = A4 + (size_t)(bb * C2 + k0 + kk) * LSEQ + l0;
        #pragma unroll
        for (int q = 0; q < 4; q++) {
            float4 v = *(const float4*)(asrc + q * 4);
            As[((q * 4 + 0) * 8 + bb) * 36 + kk] = f2tf(v.x);
            As[((q * 4 + 1) * 8 + bb) * 36 + kk] = f2tf(v.y);
            As[((q * 4 + 2) * 8 + bb) * 36 + kk] = f2tf(v.z);
            As[((q * 4 + 3) * 8 + bb) * 36 + kk] = f2tf(v.w);
        }
        #pragma unroll
        for (int q = 0; q < 4; q++) {
            float4 v = *(const float4*)(W + (size_t)(n0 + br + q * 32) * K + k0 + bc);
            uint4 u = make_uint4(__float_as_uint(v.x), __float_as_uint(v.y),
                                 __float_as_uint(v.z), __float_as_uint(v.w));
            *(uint4*)(Bs + (br + q * 32) * 36 + bc) = u;
        }
        __syncthreads();

        #pragma unroll
        for (int ks = 0; ks < 4; ks++) {
            uint32_t kkb = ks * 32;
            uint32_t a[2][4], b[8][2];
            ldsm4(a[0][0], a[0][1], a[0][2], a[0][3], abase + aoff[0] + kkb);
            ldsm4(a[1][0], a[1][1], a[1][2], a[1][3], abase + aoff[1] + kkb);
            ldsm4(b[0][0], b[0][1], b[1][0], b[1][1], bbase + boff[0] + kkb);
            ldsm4(b[2][0], b[2][1], b[3][0], b[3][1], bbase + boff[1] + kkb);
            ldsm4(b[4][0], b[4][1], b[5][0], b[5][1], bbase + boff[2] + kkb);
            ldsm4(b[6][0], b[6][1], b[7][0], b[7][1], bbase + boff[3] + kkb);
            #pragma unroll
            for (int mi = 0; mi < 2; mi++)
                #pragma unroll
                for (int nf = 0; nf < 8; nf++)
                    asm volatile(
                        "mma.sync.aligned.m16n8k8.row.col.f32.tf32.tf32.f32 "
                        "{%0,%1,%2,%3}, {%4,%5,%6,%7}, {%8,%9}, {%0,%1,%2,%3};"
                        : "+f"(acc[mi][nf][0]), "+f"(acc[mi][nf][1]),
                          "+f"(acc[mi][nf][2]), "+f"(acc[mi][nf][3])
                        : "r"(a[mi][0]), "r"(a[mi][1]), "r"(a[mi][2]), "r"(a[mi][3]),
                          "r"(b[nf][0]), "r"(b[nf][1]));
        }
        __syncthreads();
    }

    #pragma unroll
    for (int mi = 0; mi < 2; mi++) {
        #pragma unroll
        for (int nf = 0; nf < 8; nf++) {
            int n = n0 + wn * 64 + nf * 8 + tig * 2;
            int r0 = m0 + wm * 32 + mi * 16 + g;
            #pragma unroll
            for (int h = 0; h < 2; h++) {
                int m = r0 + h * 8;
                int l = m >> 3;
                float v0 = acc[mi][nf][h * 2 + 0] + bias[n];
                float v1 = acc[mi][nf][h * 2 + 1] + bias[n + 1];
                v0 = tfr(v0 * BNS * e0[n] + e1[n] + posv(ps, pc, l, n));
                v1 = tfr(v1 * BNS * e0[n + 1] + e1[n + 1] + posv(ps, pc, l, n + 1));
                *(float2*)(C + (size_t)m * C1 + n) = make_float2(v0, v1);
            }
        }
    }
}

// ---------------- cosFormer KV accumulation (partial over L/8 chunk) ----------------
__global__ void kv_partial_kernel(const float* __restrict__ Kn, const float* __restrict__ V,
                                  float* __restrict__ partial) {
    int head = blockIdx.y, chunk = blockIdx.x;
    int batch = head >> 3, hh = head & 7;
    int tid = threadIdx.x;
    int g = tid >> 5, m = tid & 31;
    __shared__ float sk[8][64];
    __shared__ float sv[8][32];
    float acc[8] = {};
    int l0 = chunk * 392;
    for (int lt = 0; lt < 392; lt += 8) {
        int l = l0 + lt + g;
        float wi = (float)(l + 1) * (1.0f / LSEQ);
        float sw, cw; sincosf(wi, &sw, &cw);
        int off = ((l << 3) + batch) * C1 + hh * HDIM + m;
        float kv_ = Kn[off];
        sk[g][m] = kv_ * cw;
        sk[g][32 + m] = kv_ * sw;
        sv[g][m] = V[off];
        __syncthreads();
        #pragma unroll
        for (int ll = 0; ll < 8; ll++) {
            float vvm = sv[ll][m];
            #pragma unroll
            for (int j = 0; j < 8; j++)
                acc[j] += sk[ll][g * 8 + j] * vvm;
        }
        __syncthreads();
    }
    #pragma unroll
    for (int j = 0; j < 8; j++)
        partial[((head * 8 + chunk) * 64 + (g * 8 + j)) * 32 + m] = acc[j];
}

// ---------------- attn = Q_ @ KV (KV reduced from partials), RMSNorm; strip-offset -------
__global__ void attn_kernel(const float* __restrict__ Q, const float* __restrict__ partial,
                            const float* __restrict__ rms_w, float* __restrict__ attnOut,
                            int strip0) {
    int head = blockIdx.y, strip = blockIdx.x + strip0;
    int batch = head >> 3, hh = head & 7;
    int tid = threadIdx.x;
    __shared__ float skv[64][32];
    __shared__ float sq[8][32];
    __shared__ float srw[32];
    for (int i = tid; i < 2048; i += 256) {
        float s = 0.f;
        #pragma unroll
        for (int ch = 0; ch < 8; ch++) s += partial[(head * 8 + ch) * 2048 + i];
        skv[i >> 5][i & 31] = s;
    }
    if (tid < 32) srw[tid] = rms_w[tid];
    __syncthreads();
    int warp = tid >> 5, m = tid & 31;
    int lend = strip * 392 + 392;
    for (int lt = strip * 392; lt < lend; lt += 8) {
        int l = lt + warp;
        sq[warp][m] = Q[((l << 3) + batch) * C1 + hh * HDIM + m];
        __syncthreads();
        float wi = (float)(l + 1) * (1.0f / LSEQ);
        float sw, cw; sincosf(wi, &sw, &cw);
        float s1 = 0.f, s2 = 0.f;
        #pragma unroll
        for (int d = 0; d < 32; d++) {
            float q = sq[warp][d];
            s1 += q * skv[d][m];
            s2 += q * skv[32 + d][m];
        }
        float a = cw * s1 + sw * s2;
        float ss = a * a;
        #pragma unroll
        for (int o = 16; o; o >>= 1) ss += __shfl_xor_sync(0xffffffffu, ss, o);
        float r = rsqrtf(ss * (1.0f / 32.0f) + 1e-6f);
        attnOut[((l << 3) + batch) * C1 + hh * HDIM + m] = tfr(srw[m] * a * r);
        __syncthreads();
    }
}

// ---------------- bilinear x2 upsample, 4 outputs/thread ----------------
__device__ __forceinline__ float4 up4(const float* __restrict__ src, int y, int j) {
    int ih = y >> 1;
    int ra = (y & 1) ? ih : ih - 1;
    float wa = (y & 1) ? 0.75f : 0.25f;
    float wb = 1.0f - wa;
    int rb = min(ra + 1, 55);
    ra = max(ra, 0);
    const float* pa = src + ra * 56;
    const float* pb = src + rb * 56;
    int cm1 = max(2 * j - 1, 0);
    int c0 = 2 * j, c1 = 2 * j + 1;
    int c2 = min(2 * j + 2, 55);
    float fm1 = wa * pa[cm1] + wb * pb[cm1];
    float f0  = wa * pa[c0]  + wb * pb[c0];
    float f1  = wa * pa[c1]  + wb * pb[c1];
    float f2  = wa * pa[c2]  + wb * pb[c2];
    float4 o;
    o.x = 0.25f * fm1 + 0.75f * f0;
    o.y = 0.75f * f0 + 0.25f * f1;
    o.z = 0.25f * f0 + 0.75f * f1;
    o.w = 0.75f * f1 + 0.25f * f2;
    return o;
}

__global__ void up_a3_kernel(const float* __restrict__ sp, const float* __restrict__ a3,
                             float* __restrict__ outp) {
    int idx = blockIdx.x * 256 + threadIdx.x;       // 8*256*112*28 quads
    int j = idx % 28; int t = idx / 28; int y = t % 112; int bc = t / 112;
    float4 v = up4(sp + (size_t)bc * LSEQ, y, j);
    size_t o = ((size_t)bc * 112 + y) * 112 + 4 * j;
    float4 m = *(const float4*)(a3 + o);
    v.x *= m.x; v.y *= m.y; v.z *= m.z; v.w *= m.w;
    *(float4*)(outp + o) = v;
}

__global__ void up_a4_kernel(const float* __restrict__ a4, float* __restrict__ outp) {
    int idx = blockIdx.x * 256 + threadIdx.x;       // 8*512*112*28 quads
    int j = idx % 28; int t = idx / 28; int y = t % 112; int bc = t / 112;
    float4 v = up4(a4 + (size_t)bc * LSEQ, y, j);
    *(float4*)(outp + ((size_t)bc * 112 + y) * 112 + 4 * j) = v;
}

// ---------------- launch ----------------
extern "C" void kernel_launch(void* const* d_in, const int* in_sizes, int n_in,
                              void* d_out, int out_size) {
    const float* a3     = (const float*)d_in[0];
    const float* a4     = (const float*)d_in[1];
    const float* conv_w = (const float*)d_in[2];
    const float* conv_b = (const float*)d_in[3];
    const float* bn_w   = (const float*)d_in[4];
    const float* bn_b   = (const float*)d_in[5];
    const float* q_w    = (const float*)d_in[6];
    const float* q_b    = (const float*)d_in[7];
    const float* q_ln_w = (const float*)d_in[8];
    const float* q_ln_b = (const float*)d_in[9];
    const float* k_w    = (const float*)d_in[10];
    const float* k_b    = (const float*)d_in[11];
    const float* k_ln_w = (const float*)d_in[12];
    const float* k_ln_b = (const float*)d_in[13];
    const float* v_w    = (const float*)d_in[14];
    const float* v_b    = (const float*)d_in[15];
    const float* o_w    = (const float*)d_in[16];
    const float* o_b    = (const float*)d_in[17];
    const float* rms_w  = (const float*)d_in[18];
    const float* l1_w   = (const float*)d_in[19];
    const float* l1_b   = (const float*)d_in[20];
    const float* l2_w   = (const float*)d_in[21];
    const float* l2_b   = (const float*)d_in[22];
    const float* n1_w   = (const float*)d_in[23];
    const float* n1_b   = (const float*)d_in[24];
    const float* n2_w   = (const float*)d_in[25];
    const float* n2_b   = (const float*)d_in[26];
    float* out = (float*)d_out;

    float *p_res, *p_X3, *p_X4, *p_Q, *p_K, *p_V;
    float *p_attn, *p_out1, *p_out1tf, *p_out2, *p_sp, *p_H, *p_part, *p_ps, *p_pc;
    float *p_wc, *p_wq, *p_wk, *p_wv, *p_wo, *p_wl1, *p_wl2;
    cudaGetSymbolAddress((void**)&p_res, g_res);
    cudaGetSymbolAddress((void**)&p_X3, g_X3);
    cudaGetSymbolAddress((void**)&p_X4, g_X4);
    cudaGetSymbolAddress((void**)&p_Q, g_Q);
    cudaGetSymbolAddress((void**)&p_K, g_K);
    cudaGetSymbolAddress((void**)&p_V, g_V);
    cudaGetSymbolAddress((void**)&p_attn, g_attn);
    cudaGetSymbolAddress((void**)&p_out1, g_out1);
    cudaGetSymbolAddress((void**)&p_out1tf, g_out1tf);
    cudaGetSymbolAddress((void**)&p_out2, g_out2);
    cudaGetSymbolAddress((void**)&p_sp, g_sp);
    cudaGetSymbolAddress((void**)&p_H, g_H);
    cudaGetSymbolAddress((void**)&p_part, g_part);
    cudaGetSymbolAddress((void**)&p_ps, g_psin);
    cudaGetSymbolAddress((void**)&p_pc, g_pcos);
    cudaGetSymbolAddress((void**)&p_wc, g_wc);
    cudaGetSymbolAddress((void**)&p_wq, g_wq);
    cudaGetSymbolAddress((void**)&p_wk, g_wk);
    cudaGetSymbolAddress((void**)&p_wv, g_wv);
    cudaGetSymbolAddress((void**)&p_wo, g_wo);
    cudaGetSymbolAddress((void**)&p_wl1, g_wl1);
    cudaGetSymbolAddress((void**)&p_wl2, g_wl2);

    // exactly 3 side streams / 7 events (validated against harness mem checkpoint)
    static cudaStream_t sW = 0, sU = 0, sQ = 0;
    static cudaEvent_t evRoot = 0, evW = 0, evU = 0, evQ = 0, evP = 0, evC = 0, evV = 0;
    if (sW == 0) {
        cudaStreamCreateWithFlags(&sW, cudaStreamNonBlocking);
        cudaStreamCreateWithFlags(&sU, cudaStreamNonBlocking);
        cudaStreamCreateWithFlags(&sQ, cudaStreamNonBlocking);
        cudaEventCreateWithFlags(&evRoot, cudaEventDisableTiming);
        cudaEventCreateWithFlags(&evW, cudaEventDisableTiming);
        cudaEventCreateWithFlags(&evU, cudaEventDisableTiming);
        cudaEventCreateWithFlags(&evQ, cudaEventDisableTiming);
        cudaEventCreateWithFlags(&evP, cudaEventDisableTiming);
        cudaEventCreateWithFlags(&evC, cudaEventDisableTiming);
        cudaEventCreateWithFlags(&evV, cudaEventDisableTiming);
    }

    const int SMEM_CA = (2 * 128 * 36 + 2 * 128 * 36) * 4;   // 73728 bytes
    const int SMEM_LN = (2 * 64 * 36 + 2 * 256 * 36) * 4;    // 92160 bytes
    cudaFuncSetAttribute(gemm_ca<256, 0>, cudaFuncAttributeMaxDynamicSharedMemorySize, SMEM_CA);
    cudaFuncSetAttribute(gemm_ca<256, 1>, cudaFuncAttributeMaxDynamicSharedMemorySize, SMEM_CA);
    cudaFuncSetAttribute(gemm_ln<256, 0>, cudaFuncAttributeMaxDynamicSharedMemorySize, SMEM_LN);
    cudaFuncSetAttribute(gemm_ln<256, 1>, cudaFuncAttributeMaxDynamicSharedMemorySize, SMEM_LN);
    cudaFuncSetAttribute(gemm_ln<1024, 1>, cudaFuncAttributeMaxDynamicSharedMemorySize, SMEM_LN);

    dim3 b328(32, 8);

    // row-half pointer offsets (tail pipelining)
    const size_t offC = (size_t)MHALF * C1;      // [t, 256] tensors
    const size_t offH = (size_t)MHALF * 1024;    // FFN hidden

    // ---- fork side streams from the capture-origin (legacy) stream ----
    cudaEventRecord(evRoot, 0);
    cudaStreamWaitEvent(sW, evRoot, 0);
    cudaStreamWaitEvent(sU, evRoot, 0);
    cudaStreamWaitEvent(sQ, evRoot, 0);

    // sW: all weight tf32 conversions in one launch
    tfconv_all<<<896, 256, 0, sW>>>(conv_w, q_w, k_w, v_w, o_w, l1_w, l2_w,
                                    p_wc, p_wq, p_wk, p_wv, p_wo, p_wl1, p_wl2);
    cudaEventRecord(evW, sW);

    // sU: a4 bilinear upsample (independent); later carries V + half-0 tail chain
    up_a4_kernel<<<50176, 256, 0, sU>>>(a4, out + 25690112);

    // sQ: pos tables + a3 pool/transpose, then fused Q projection
    pos_small_kernel<<<14, 256, 0, sQ>>>(p_ps, p_pc);
    pool_transpose_tokens<<<dim3(98, 8, 8), b328, 0, sQ>>>(a3, p_res, p_X3, p_ps, p_pc);
    cudaEventRecord(evP, sQ);
    cudaStreamWaitEvent(sQ, evW, 0);
    gemm_ln<256, 0><<<392, 256, SMEM_LN, sQ>>>(p_X3, p_wq, q_b, q_ln_w, q_ln_b,
                                               nullptr, p_Q, nullptr);
    cudaEventRecord(evQ, sQ);

    // main: conv1x1 + BN + pos -> X4 (needs weights + pos tables from sQ)
    cudaStreamWaitEvent(0, evW, 0);
    cudaStreamWaitEvent(0, evP, 0);
    gemm_conv<<<dim3(196, 2), 256>>>(a4, p_wc, conv_b, p_X4, bn_w, bn_b, p_ps, p_pc);
    cudaEventRecord(evC, 0);

    // sU: V projection (needs X4) — overlaps K gemm_ln on main
    cudaStreamWaitEvent(sU, evC, 0);
    gemm_ca<256, 0><<<dim3(196, 2), 256, SMEM_CA, sU>>>(p_X4, p_wv, v_b, p_V, C1);
    cudaEventRecord(evV, sU);

    // main: fused K projection + LN + L2
    gemm_ln<256, 0><<<392, 256, SMEM_LN>>>(p_X4, p_wk, k_b, k_ln_w, k_ln_b,
                                           nullptr, p_K, nullptr);

    // main: KV accumulation (needs full K, V); re-record evP as "KV partials ready"
    cudaStreamWaitEvent(0, evV, 0);
    kv_partial_kernel<<<dim3(8, 64), 256>>>(p_K, p_V, p_part);
    cudaEventRecord(evP, 0);
    cudaStreamWaitEvent(0, evQ, 0);

    // ---- tail pipelining: half-0 on sU, half-1 on main (row-disjoint) ----
    // sU half-0: attn strips 0..3 (l < 1568, t < 12544) then O/FFN chain
    cudaStreamWaitEvent(sU, evP, 0);
    cudaStreamWaitEvent(sU, evQ, 0);
    attn_kernel<<<dim3(4, 64), 256, 0, sU>>>(p_Q, p_part, rms_w, p_attn, 0);
    gemm_ln<256, 1><<<196, 256, SMEM_LN, sU>>>(p_attn, p_wo, o_b, n1_w, n1_b,
                                               p_res, p_out1, p_out1tf);
    gemm_ca<256, 1><<<dim3(98, 8), 256, SMEM_CA, sU>>>(p_out1tf, p_wl1, l1_b, p_H, 1024);
    gemm_ln<1024, 1><<<196, 256, SMEM_LN, sU>>>(p_H, p_wl2, l2_b, n2_w, n2_b,
                                                p_out1, p_out2, nullptr);
    transpose_to_spatial<<<dim3(49, 8, 8), b328, 0, sU>>>(p_out2, p_sp, 0);
    cudaEventRecord(evU, sU);

    // main half-1: attn strips 4..7 then O/FFN chain (pointer-offset rows)
    attn_kernel<<<dim3(4, 64), 256>>>(p_Q, p_part, rms_w, p_attn, 4);
    gemm_ln<256, 1><<<196, 256, SMEM_LN>>>(p_attn + offC, p_wo, o_b, n1_w, n1_b,
                                           p_res + offC, p_out1 + offC, p_out1tf + offC);
    gemm_ca<256, 1><<<dim3(98, 8), 256, SMEM_CA>>>(p_out1tf + offC, p_wl1, l1_b,
                                                   p_H + offH, 1024);
    gemm_ln<1024, 1><<<196, 256, SMEM_LN>>>(p_H + offH, p_wl2, l2_b, n2_w, n2_b,
                                            p_out1 + offC, p_out2 + offC, nullptr);
    transpose_to_spatial<<<dim3(49, 8, 8), b328>>>(p_out2, p_sp, 49);

    // join half-0 (and up_a4 upstream on sU), then final upsample+mask
    cudaStreamWaitEvent(0, evU, 0);
    up_a3_kernel<<<25088, 256>>>(p_sp, a3, out);
}